// round 15
// baseline (speedup 1.0000x reference)
#include <cuda_runtime.h>
#include <cuda_bf16.h>
#include <math.h>
#include <stdint.h>

// Problem: x[N=2,T=16,S=256,D=1024]
// qkv = x @ Wqkv[1024,3072]; heads=8, Dh=64, scale=0.125
// spatial attn over S per (n,t,h); temporal attn over T per (n,s,h)
// out = concat(x_s, x_t) @ Wproj + bproj

#define NB 2
#define TB 16
#define SB 256
#define DB 1024
#define ROWS (NB*TB*SB)      // 8192
#define THREE_D (3*DB)       // 3072
#define HEADS 8
#define DH 64

// Scratch (device globals; allocation-free per harness rules)
__device__ float g_qkv[(size_t)ROWS * THREE_D];          // fp32 qkv, ~100.7MB
__device__ __nv_bfloat16 g_xh[(size_t)ROWS * DB];        // x hi/lo
__device__ __nv_bfloat16 g_xl[(size_t)ROWS * DB];
__device__ __nv_bfloat16 g_wqh[(size_t)DB * THREE_D];    // Wqkv hi/lo
__device__ __nv_bfloat16 g_wql[(size_t)DB * THREE_D];
__device__ __nv_bfloat16 g_wph[(size_t)DB * DB];         // Wproj hi/lo
__device__ __nv_bfloat16 g_wpl[(size_t)DB * DB];
__device__ __nv_bfloat16 g_ah[(size_t)ROWS * DB];        // attn out hi/lo
__device__ __nv_bfloat16 g_al[(size_t)ROWS * DB];

// ---------------------------------------------------------------------------
// helpers
// ---------------------------------------------------------------------------
typedef unsigned long long u64t;

__device__ __forceinline__ uint32_t sm_u32(const void* p) {
    return (uint32_t)__cvta_generic_to_shared(p);
}
__device__ __forceinline__ void cp16(void* sdst, const void* gsrc) {
    asm volatile("cp.async.cg.shared.global [%0], [%1], 16;\n"
                 :: "r"(sm_u32(sdst)), "l"(gsrc));
}
__device__ __forceinline__ void cp_commit() {
    asm volatile("cp.async.commit_group;\n");
}
template<int NPEND>
__device__ __forceinline__ void cp_wait() {
    asm volatile("cp.async.wait_group %0;\n" :: "n"(NPEND));
}
__device__ __forceinline__ void ldsm_x4(uint32_t* r, uint32_t addr) {
    asm volatile("ldmatrix.sync.aligned.m8n8.x4.shared.b16 {%0,%1,%2,%3}, [%4];"
                 : "=r"(r[0]), "=r"(r[1]), "=r"(r[2]), "=r"(r[3]) : "r"(addr));
}
__device__ __forceinline__ void ldsm_x4_t(uint32_t* r, uint32_t addr) {
    asm volatile("ldmatrix.sync.aligned.m8n8.x4.trans.shared.b16 {%0,%1,%2,%3}, [%4];"
                 : "=r"(r[0]), "=r"(r[1]), "=r"(r[2]), "=r"(r[3]) : "r"(addr));
}
__device__ __forceinline__ void mma16816(float* c, const uint32_t* a,
                                         const uint32_t* b) {
    asm volatile(
        "mma.sync.aligned.m16n8k16.row.col.f32.bf16.bf16.f32 "
        "{%0,%1,%2,%3}, {%4,%5,%6,%7}, {%8,%9}, {%0,%1,%2,%3};"
        : "+f"(c[0]), "+f"(c[1]), "+f"(c[2]), "+f"(c[3])
        : "r"(a[0]), "r"(a[1]), "r"(a[2]), "r"(a[3]), "r"(b[0]), "r"(b[1]));
}
__device__ __forceinline__ void split2(float v, uint16_t& hi, uint16_t& lo) {
    __nv_bfloat16 h = __float2bfloat16(v);
    __nv_bfloat16 l = __float2bfloat16(v - __bfloat162float(h));
    hi = __bfloat16_as_ushort(h);
    lo = __bfloat16_as_ushort(l);
}

// ---- packed f32x2 (Blackwell FFMA2, only reachable via PTX fma.rn.f32x2) ----
__device__ __forceinline__ u64t pack2(float lo, float hi) {
    u64t r; asm("mov.b64 %0, {%1, %2};" : "=l"(r) : "f"(lo), "f"(hi));
    return r;
}
__device__ __forceinline__ void unpack2(u64t v, float& lo, float& hi) {
    asm("mov.b64 {%0, %1}, %2;" : "=f"(lo), "=f"(hi) : "l"(v));
}
__device__ __forceinline__ u64t ffma2(u64t a, u64t b, u64t c) {
    u64t d;
    asm("fma.rn.f32x2 %0, %1, %2, %3;" : "=l"(d) : "l"(a), "l"(b), "l"(c));
    return d;
}

// ---------------------------------------------------------------------------
// Elementwise fp32 -> (bf16 hi, bf16 lo) split, float4-vectorized.
// ---------------------------------------------------------------------------
__global__ __launch_bounds__(256) void split_kernel(
    const float* __restrict__ in, __nv_bfloat16* __restrict__ hi,
    __nv_bfloat16* __restrict__ lo, int n4)
{
    const int i = blockIdx.x * 256 + threadIdx.x;
    if (i >= n4) return;
    float4 v = ((const float4*)in)[i];
    uint16_t h0,h1,h2,h3,l0,l1,l2,l3;
    split2(v.x,h0,l0); split2(v.y,h1,l1);
    split2(v.z,h2,l2); split2(v.w,h3,l3);
    uint2 uh, ul;
    uh.x = (uint32_t)h0 | ((uint32_t)h1 << 16);
    uh.y = (uint32_t)h2 | ((uint32_t)h3 << 16);
    ul.x = (uint32_t)l0 | ((uint32_t)l1 << 16);
    ul.y = (uint32_t)l2 | ((uint32_t)l3 << 16);
    ((uint2*)hi)[i] = uh;
    ((uint2*)lo)[i] = ul;
}

// ---------------------------------------------------------------------------
// Tensor-core GEMM (R9 version, measured 389us/65.3% tensor):
// pre-split bf16 inputs, cp.async 2-stage double buffer.
// C = Ah@Bh + Ah@Bl + Al@Bh (+bias), fp32 accum/out.
// BM=BN=128, BK=32, 256 thr = 8 warps (4m x 2n). 2 CTAs/SM.
// ---------------------------------------------------------------------------
#define APAD 40     // A row stride (elements): 80B
#define BPAD 136    // B row stride: 272B
#define A_ELS (128 * APAD)
#define B_ELS (32 * BPAD)
#define STAGE_ELS (2 * A_ELS + 2 * B_ELS)
#define GEMM_SMEM (2 * STAGE_ELS * 2)   // bytes, 2 stages (~74 KB)

template<bool BIAS>
__global__ __launch_bounds__(256, 2) void gemm_pre(
    const __nv_bfloat16* __restrict__ Ah, const __nv_bfloat16* __restrict__ Al,
    const __nv_bfloat16* __restrict__ Bh, const __nv_bfloat16* __restrict__ Bl,
    const float* __restrict__ bias, float* __restrict__ C,
    int M, int N, int K)
{
    extern __shared__ __nv_bfloat16 smem[];

    const int tid  = threadIdx.x;
    const int lane = tid & 31;
    const int warp = tid >> 5;
    const int m_base = (warp & 3) * 32;
    const int n_base = (warp >> 2) * 64;
    const int blockM = blockIdx.y * 128;
    const int blockN = blockIdx.x * 128;

    const int aRow0 = tid >> 2, aC0 = (tid & 3) << 3;
    const int aRow1 = (tid + 256) >> 2, aC1 = ((tid + 256) & 3) << 3;
    const int bRow0 = tid >> 4, bC0 = (tid & 15) << 3;
    const int bRow1 = (tid + 256) >> 4, bC1 = ((tid + 256) & 15) << 3;

    float acc[2][8][4];
    #pragma unroll
    for (int i = 0; i < 2; i++)
        #pragma unroll
        for (int j = 0; j < 8; j++)
            #pragma unroll
            for (int q = 0; q < 4; q++) acc[i][j][q] = 0.f;

    auto load_tile = [&](int stage, int k0) {
        __nv_bfloat16* sAh = smem + stage * STAGE_ELS;
        __nv_bfloat16* sAl = sAh + A_ELS;
        __nv_bfloat16* sBh = sAl + A_ELS;
        __nv_bfloat16* sBl = sBh + B_ELS;
        cp16(sAh + aRow0 * APAD + aC0, Ah + (size_t)(blockM + aRow0) * K + k0 + aC0);
        cp16(sAh + aRow1 * APAD + aC1, Ah + (size_t)(blockM + aRow1) * K + k0 + aC1);
        cp16(sAl + aRow0 * APAD + aC0, Al + (size_t)(blockM + aRow0) * K + k0 + aC0);
        cp16(sAl + aRow1 * APAD + aC1, Al + (size_t)(blockM + aRow1) * K + k0 + aC1);
        cp16(sBh + bRow0 * BPAD + bC0, Bh + (size_t)(k0 + bRow0) * N + blockN + bC0);
        cp16(sBh + bRow1 * BPAD + bC1, Bh + (size_t)(k0 + bRow1) * N + blockN + bC1);
        cp16(sBl + bRow0 * BPAD + bC0, Bl + (size_t)(k0 + bRow0) * N + blockN + bC0);
        cp16(sBl + bRow1 * BPAD + bC1, Bl + (size_t)(k0 + bRow1) * N + blockN + bC1);
    };

    const int NT = K >> 5;   // K/32
    load_tile(0, 0);
    cp_commit();

    for (int kt = 0; kt < NT; kt++) {
        if (kt + 1 < NT) {
            load_tile((kt + 1) & 1, (kt + 1) << 5);
            cp_commit();
            cp_wait<1>();
        } else {
            cp_wait<0>();
        }
        __syncthreads();

        const __nv_bfloat16* sAh = smem + (kt & 1) * STAGE_ELS;
        const __nv_bfloat16* sAl = sAh + A_ELS;
        const __nv_bfloat16* sBh = sAl + A_ELS;
        const __nv_bfloat16* sBl = sBh + B_ELS;

        #pragma unroll
        for (int ks = 0; ks < 2; ks++) {
            const int kk = ks * 16;
            uint32_t ah[2][4], al[2][4];
            #pragma unroll
            for (int mf = 0; mf < 2; mf++) {
                const int row = m_base + mf * 16 + (lane & 15);
                const int col = kk + ((lane >> 4) << 3);
                ldsm_x4(ah[mf], sm_u32(sAh + row * APAD + col));
                ldsm_x4(al[mf], sm_u32(sAl + row * APAD + col));
            }
            #pragma unroll
            for (int ng = 0; ng < 4; ng++) {
                const int brow = kk + (lane & 15);
                const int bcol = n_base + ng * 16 + ((lane >> 4) << 3);
                uint32_t bh[4], bl[4];
                ldsm_x4_t(bh, sm_u32(sBh + brow * BPAD + bcol));
                ldsm_x4_t(bl, sm_u32(sBl + brow * BPAD + bcol));
                #pragma unroll
                for (int p = 0; p < 3; p++) {
                    const uint32_t* ap0 = (p == 2) ? al[0] : ah[0];
                    const uint32_t* ap1 = (p == 2) ? al[1] : ah[1];
                    const uint32_t* bp = (p == 1) ? bl : bh;
                    mma16816(acc[0][ng*2+0], ap0, bp + 0);
                    mma16816(acc[1][ng*2+0], ap1, bp + 0);
                    mma16816(acc[0][ng*2+1], ap0, bp + 2);
                    mma16816(acc[1][ng*2+1], ap1, bp + 2);
                }
            }
        }
        __syncthreads();
    }

    #pragma unroll
    for (int mf = 0; mf < 2; mf++) {
        const int r0 = blockM + m_base + mf * 16 + (lane >> 2);
        #pragma unroll
        for (int nf = 0; nf < 8; nf++) {
            const int cN = blockN + n_base + nf * 8 + (lane & 3) * 2;
            float2 v0 = make_float2(acc[mf][nf][0], acc[mf][nf][1]);
            float2 v1 = make_float2(acc[mf][nf][2], acc[mf][nf][3]);
            if (BIAS) {
                const float b0 = bias[cN], b1 = bias[cN + 1];
                v0.x += b0; v0.y += b1; v1.x += b0; v1.y += b1;
            }
            *(float2*)(C + (size_t)r0 * N + cN) = v0;
            *(float2*)(C + (size_t)(r0 + 8) * N + cN) = v1;
        }
    }
}

// ---------------------------------------------------------------------------
// Fused attention, paired-lane layout: each query handled by 2 adjacent lanes,
// each lane owning 32 of the 64 head dims (halves registers -> more warps).
// 512 threads/block.
//   Blocks [0,256): spatial — one (n*t, head); K/V (256x64 x2) staged in smem.
//   Blocks [256,512): temporal — 2 (n,s) per block; K/V direct from gmem.
// Full score = half-dot + __shfl_xor(.,1). Outputs bf16 hi/lo split.
// ---------------------------------------------------------------------------
#define ATTN_SMEM (2 * SB * DH * 4)   // 128KB (spatial staging)

// store 32 elements (16 u64 accumulators) as hi/lo bf16
__device__ __forceinline__ void store_hi_lo32(
    __nv_bfloat16* oh, __nv_bfloat16* ol, size_t obase, const u64t* acc2,
    float inv)
{
    #pragma unroll
    for (int d8 = 0; d8 < 4; d8++) {
        uint4 uh, ul;
        uint16_t hh[8], lt[8];
        #pragma unroll
        for (int e2 = 0; e2 < 4; e2++) {
            float a0, a1;
            unpack2(acc2[d8 * 4 + e2], a0, a1);
            split2(a0 * inv, hh[e2*2+0], lt[e2*2+0]);
            split2(a1 * inv, hh[e2*2+1], lt[e2*2+1]);
        }
        uh.x = (uint32_t)hh[0] | ((uint32_t)hh[1] << 16);
        uh.y = (uint32_t)hh[2] | ((uint32_t)hh[3] << 16);
        uh.z = (uint32_t)hh[4] | ((uint32_t)hh[5] << 16);
        uh.w = (uint32_t)hh[6] | ((uint32_t)hh[7] << 16);
        ul.x = (uint32_t)lt[0] | ((uint32_t)lt[1] << 16);
        ul.y = (uint32_t)lt[2] | ((uint32_t)lt[3] << 16);
        ul.z = (uint32_t)lt[4] | ((uint32_t)lt[5] << 16);
        ul.w = (uint32_t)lt[6] | ((uint32_t)lt[7] << 16);
        *(uint4*)(oh + obase + d8 * 8) = uh;
        *(uint4*)(ol + obase + d8 * 8) = ul;
    }
}

__global__ __launch_bounds__(512) void fused_attn(
    const float* __restrict__ qkv,
    __nv_bfloat16* __restrict__ oh, __nv_bfloat16* __restrict__ ol)
{
    extern __shared__ float sm[];
    const int tid = threadIdx.x;
    const float scale = 0.125f;

    if (blockIdx.x < 256) {
        // ---------------- spatial: one (nt, h); lane-pair per query --------
        float* Ks = sm;             // [256][64]
        float* Vs = sm + SB * DH;   // [256][64]
        const int inst = blockIdx.x;
        const int h = inst & 7;
        const int nt = inst >> 3;
        const int q = tid >> 1;        // query index 0..255
        const int half = tid & 1;      // which 32-dim half

        const float* base = qkv + (size_t)nt * SB * THREE_D;

        for (int i = tid; i < SB * 16; i += 512) {
            const int row = i >> 4;
            const int c4 = (i & 15) << 2;
            const float* rb = base + (size_t)row * THREE_D + h * DH;
            *(float4*)(Ks + row * DH + c4) = *(const float4*)(rb + 1024 + c4);
            *(float4*)(Vs + row * DH + c4) = *(const float4*)(rb + 2048 + c4);
        }

        u64t q2[16];
        {
            const u64t* qp2 =
                (const u64t*)(base + (size_t)q * THREE_D + h * DH + half * 32);
            #pragma unroll
            for (int i = 0; i < 16; i++) q2[i] = qp2[i];
        }
        __syncthreads();

        float m = -INFINITY, l = 0.f;
        u64t acc2[16];
        #pragma unroll
        for (int i = 0; i < 16; i++) acc2[i] = 0ull;

        for (int jt = 0; jt < SB; jt += 8) {
            float s8[8];
            float tmax = -INFINITY;
            #pragma unroll
            for (int u = 0; u < 8; u++) {
                const u64t* kj2 =
                    (const u64t*)(Ks + (jt + u) * DH + half * 32);
                u64t d2a = 0ull, d2b = 0ull;
                #pragma unroll
                for (int i = 0; i < 16; i += 2) {
                    d2a = ffma2(q2[i],     kj2[i],     d2a);
                    d2b = ffma2(q2[i + 1], kj2[i + 1], d2b);
                }
                float a0, a1, b0, b1;
                unpack2(d2a, a0, a1);
                unpack2(d2b, b0, b1);
                float hsum = (a0 + b0) + (a1 + b1);
                hsum += __shfl_xor_sync(0xFFFFFFFFu, hsum, 1);
                s8[u] = hsum * scale;
                tmax = fmaxf(tmax, s8[u]);
            }
            const float mn = fmaxf(m, tmax);
            const float c = __expf(m - mn);
            l *= c;
            const u64t cc = pack2(c, c);
            #pragma unroll
            for (int i = 0; i < 16; i++) acc2[i] = ffma2(acc2[i], cc, 0ull);
            m = mn;
            #pragma unroll
            for (int u = 0; u < 8; u++) {
                const float p = __expf(s8[u] - m);
                l += p;
                const u64t pp = pack2(p, p);
                const u64t* vj2 =
                    (const u64t*)(Vs + (jt + u) * DH + half * 32);
                #pragma unroll
                for (int i = 0; i < 16; i++)
                    acc2[i] = ffma2(pp, vj2[i], acc2[i]);
            }
        }

        const size_t obase =
            ((size_t)nt * SB + q) * DB + h * DH + half * 32;  // cols [0,512)
        store_hi_lo32(oh, ol, obase, acc2, 1.f / l);
    } else {
        // ------------- temporal: 2 (n,s) per block; lane-pair per (t,h) ----
        const int bi = blockIdx.x - 256;       // 0..255
        const int nsh = tid >> 8;              // which of 2 (n,s)
        const int ns = bi * 2 + nsh;
        const int n = ns >> 8;
        const int s = ns & 255;
        const int lt = tid & 255;
        const int t = lt >> 4;                 // 0..15
        const int h = (lt >> 1) & 7;           // 0..7
        const int half = lt & 1;               // 0..1

        const size_t tstride = (size_t)SB * THREE_D;
        const float* rowbase = qkv + ((size_t)(n * TB) * SB + s) * THREE_D;

        u64t q2[16];
        {
            const u64t* qp2 = (const u64t*)(rowbase + t * tstride + 512 +
                                            h * DH + half * 32);
            #pragma unroll
            for (int i = 0; i < 16; i++) q2[i] = qp2[i];
        }

        float sc[TB];
        float mmax = -INFINITY;
        #pragma unroll
        for (int j = 0; j < TB; j++) {
            const u64t* kj2 = (const u64t*)(rowbase + j * tstride + 1536 +
                                            h * DH + half * 32);
            u64t d2a = 0ull, d2b = 0ull;
            #pragma unroll
            for (int i = 0; i < 16; i += 2) {
                d2a = ffma2(q2[i],     kj2[i],     d2a);
                d2b = ffma2(q2[i + 1], kj2[i + 1], d2b);
            }
            float a0, a1, b0, b1;
            unpack2(d2a, a0, a1);
            unpack2(d2b, b0, b1);
            float hsum = (a0 + b0) + (a1 + b1);
            hsum += __shfl_xor_sync(0xFFFFFFFFu, hsum, 1);
            sc[j] = hsum * scale;
            mmax = fmaxf(mmax, sc[j]);
        }
        float lsum = 0.f;
        #pragma unroll
        for (int j = 0; j < TB; j++) {
            sc[j] = __expf(sc[j] - mmax);
            lsum += sc[j];
        }

        u64t acc2[16];
        #pragma unroll
        for (int i = 0; i < 16; i++) acc2[i] = 0ull;
        #pragma unroll
        for (int j = 0; j < TB; j++) {
            const u64t pp = pack2(sc[j], sc[j]);
            const u64t* vj2 = (const u64t*)(rowbase + j * tstride + 2560 +
                                            h * DH + half * 32);
            #pragma unroll
            for (int i = 0; i < 16; i++)
                acc2[i] = ffma2(pp, vj2[i], acc2[i]);
        }

        const size_t obase = ((size_t)(n * TB + t) * SB + s) * DB + 512 +
                             h * DH + half * 32;   // cols [512,1024)
        store_hi_lo32(oh, ol, obase, acc2, 1.f / lsum);
    }
}

// ---------------------------------------------------------------------------
extern "C" void kernel_launch(void* const* d_in, const int* in_sizes, int n_in,
                              void* d_out, int out_size)
{
    const float* x     = (const float*)d_in[0];  // [2,16,256,1024]
    const float* Wqkv  = (const float*)d_in[1];  // [1024,3072]
    const float* Wproj = (const float*)d_in[2];  // [1024,1024]
    const float* bproj = (const float*)d_in[3];  // [1024]
    float* out = (float*)d_out;

    float *qkv_ptr;
    __nv_bfloat16 *xh, *xl, *wqh, *wql, *wph, *wpl, *ah, *al;
    cudaGetSymbolAddress((void**)&qkv_ptr, g_qkv);
    cudaGetSymbolAddress((void**)&xh, g_xh);
    cudaGetSymbolAddress((void**)&xl, g_xl);
    cudaGetSymbolAddress((void**)&wqh, g_wqh);
    cudaGetSymbolAddress((void**)&wql, g_wql);
    cudaGetSymbolAddress((void**)&wph, g_wph);
    cudaGetSymbolAddress((void**)&wpl, g_wpl);
    cudaGetSymbolAddress((void**)&ah, g_ah);
    cudaGetSymbolAddress((void**)&al, g_al);

    cudaFuncSetAttribute(gemm_pre<false>,
        cudaFuncAttributeMaxDynamicSharedMemorySize, GEMM_SMEM);
    cudaFuncSetAttribute(gemm_pre<true>,
        cudaFuncAttributeMaxDynamicSharedMemorySize, GEMM_SMEM);
    cudaFuncSetAttribute(fused_attn,
        cudaFuncAttributeMaxDynamicSharedMemorySize, ATTN_SMEM);

    // 0) pre-split inputs to bf16 hi/lo
    {
        int n4x = ROWS * DB / 4;
        split_kernel<<<n4x / 256, 256>>>(x, xh, xl, n4x);
        int n4q = DB * THREE_D / 4;
        split_kernel<<<n4q / 256, 256>>>(Wqkv, wqh, wql, n4q);
        int n4p = DB * DB / 4;
        split_kernel<<<n4p / 256, 256>>>(Wproj, wph, wpl, n4p);
    }

    // 1) qkv = x @ Wqkv : [8192,1024] x [1024,3072]
    {
        dim3 grid(THREE_D / 128, ROWS / 128);
        gemm_pre<false><<<grid, 256, GEMM_SMEM>>>(xh, xl, wqh, wql, nullptr,
                                                  qkv_ptr, ROWS, THREE_D, DB);
    }

    // 2) fused spatial (blocks 0-255) + temporal (blocks 256-511) attention
    fused_attn<<<512, 512, ATTN_SMEM>>>(qkv_ptr, ah, al);

    // 3) out = attn @ Wproj + bproj : [8192,1024] x [1024,1024]
    {
        dim3 grid(DB / 128, ROWS / 128);
        gemm_pre<true><<<grid, 256, GEMM_SMEM>>>(ah, al, wph, wpl, bproj,
                                                 out, ROWS, DB, DB);
    }
}

// round 16
// speedup vs baseline: 1.2903x; 1.2903x over previous
#include <cuda_runtime.h>
#include <cuda_bf16.h>
#include <math.h>
#include <stdint.h>

// Problem: x[N=2,T=16,S=256,D=1024]
// qkv = x @ Wqkv[1024,3072]; heads=8, Dh=64, scale=0.125
// spatial attn over S per (n,t,h); temporal attn over T per (n,s,h)
// out = concat(x_s, x_t) @ Wproj + bproj

#define NB 2
#define TB 16
#define SB 256
#define DB 1024
#define ROWS (NB*TB*SB)      // 8192
#define THREE_D (3*DB)       // 3072
#define HEADS 8
#define DH 64

// Scratch (device globals; allocation-free per harness rules)
__device__ float g_qkv[(size_t)ROWS * THREE_D];          // fp32 qkv, ~100.7MB
__device__ __nv_bfloat16 g_xh[(size_t)ROWS * DB];        // x hi/lo
__device__ __nv_bfloat16 g_xl[(size_t)ROWS * DB];
__device__ __nv_bfloat16 g_wqh[(size_t)DB * THREE_D];    // Wqkv hi/lo
__device__ __nv_bfloat16 g_wql[(size_t)DB * THREE_D];
__device__ __nv_bfloat16 g_wph[(size_t)DB * DB];         // Wproj hi/lo
__device__ __nv_bfloat16 g_wpl[(size_t)DB * DB];
__device__ __nv_bfloat16 g_ah[(size_t)ROWS * DB];        // attn out hi/lo
__device__ __nv_bfloat16 g_al[(size_t)ROWS * DB];

// ---------------------------------------------------------------------------
// helpers
// ---------------------------------------------------------------------------
typedef unsigned long long u64t;

__device__ __forceinline__ uint32_t sm_u32(const void* p) {
    return (uint32_t)__cvta_generic_to_shared(p);
}
__device__ __forceinline__ void cp16(void* sdst, const void* gsrc) {
    asm volatile("cp.async.cg.shared.global [%0], [%1], 16;\n"
                 :: "r"(sm_u32(sdst)), "l"(gsrc));
}
__device__ __forceinline__ void cp_commit() {
    asm volatile("cp.async.commit_group;\n");
}
template<int NPEND>
__device__ __forceinline__ void cp_wait() {
    asm volatile("cp.async.wait_group %0;\n" :: "n"(NPEND));
}
__device__ __forceinline__ void ldsm_x4(uint32_t* r, uint32_t addr) {
    asm volatile("ldmatrix.sync.aligned.m8n8.x4.shared.b16 {%0,%1,%2,%3}, [%4];"
                 : "=r"(r[0]), "=r"(r[1]), "=r"(r[2]), "=r"(r[3]) : "r"(addr));
}
__device__ __forceinline__ void ldsm_x4_t(uint32_t* r, uint32_t addr) {
    asm volatile("ldmatrix.sync.aligned.m8n8.x4.trans.shared.b16 {%0,%1,%2,%3}, [%4];"
                 : "=r"(r[0]), "=r"(r[1]), "=r"(r[2]), "=r"(r[3]) : "r"(addr));
}
__device__ __forceinline__ void mma16816(float* c, const uint32_t* a,
                                         const uint32_t* b) {
    asm volatile(
        "mma.sync.aligned.m16n8k16.row.col.f32.bf16.bf16.f32 "
        "{%0,%1,%2,%3}, {%4,%5,%6,%7}, {%8,%9}, {%0,%1,%2,%3};"
        : "+f"(c[0]), "+f"(c[1]), "+f"(c[2]), "+f"(c[3])
        : "r"(a[0]), "r"(a[1]), "r"(a[2]), "r"(a[3]), "r"(b[0]), "r"(b[1]));
}
__device__ __forceinline__ void split2(float v, uint16_t& hi, uint16_t& lo) {
    __nv_bfloat16 h = __float2bfloat16(v);
    __nv_bfloat16 l = __float2bfloat16(v - __bfloat162float(h));
    hi = __bfloat16_as_ushort(h);
    lo = __bfloat16_as_ushort(l);
}

// ---- packed f32x2 (Blackwell FFMA2, only reachable via PTX fma.rn.f32x2) ----
__device__ __forceinline__ u64t pack2(float lo, float hi) {
    u64t r; asm("mov.b64 %0, {%1, %2};" : "=l"(r) : "f"(lo), "f"(hi));
    return r;
}
__device__ __forceinline__ void unpack2(u64t v, float& lo, float& hi) {
    asm("mov.b64 {%0, %1}, %2;" : "=f"(lo), "=f"(hi) : "l"(v));
}
__device__ __forceinline__ u64t ffma2(u64t a, u64t b, u64t c) {
    u64t d;
    asm("fma.rn.f32x2 %0, %1, %2, %3;" : "=l"(d) : "l"(a), "l"(b), "l"(c));
    return d;
}

// ---------------------------------------------------------------------------
// Elementwise fp32 -> (bf16 hi, bf16 lo) split, float4-vectorized.
// ---------------------------------------------------------------------------
__global__ __launch_bounds__(256) void split_kernel(
    const float* __restrict__ in, __nv_bfloat16* __restrict__ hi,
    __nv_bfloat16* __restrict__ lo, int n4)
{
    const int i = blockIdx.x * 256 + threadIdx.x;
    if (i >= n4) return;
    float4 v = ((const float4*)in)[i];
    uint16_t h0,h1,h2,h3,l0,l1,l2,l3;
    split2(v.x,h0,l0); split2(v.y,h1,l1);
    split2(v.z,h2,l2); split2(v.w,h3,l3);
    uint2 uh, ul;
    uh.x = (uint32_t)h0 | ((uint32_t)h1 << 16);
    uh.y = (uint32_t)h2 | ((uint32_t)h3 << 16);
    ul.x = (uint32_t)l0 | ((uint32_t)l1 << 16);
    ul.y = (uint32_t)l2 | ((uint32_t)l3 << 16);
    ((uint2*)hi)[i] = uh;
    ((uint2*)lo)[i] = ul;
}

// ---------------------------------------------------------------------------
// Tensor-core GEMM (R9 version, measured 389us/65.3% tensor):
// pre-split bf16 inputs, cp.async 2-stage double buffer.
// C = Ah@Bh + Ah@Bl + Al@Bh (+bias), fp32 accum/out.
// BM=BN=128, BK=32, 256 thr = 8 warps (4m x 2n). 2 CTAs/SM.
// ---------------------------------------------------------------------------
#define APAD 40     // A row stride (elements): 80B
#define BPAD 136    // B row stride: 272B
#define A_ELS (128 * APAD)
#define B_ELS (32 * BPAD)
#define STAGE_ELS (2 * A_ELS + 2 * B_ELS)
#define GEMM_SMEM (2 * STAGE_ELS * 2)   // bytes, 2 stages (~74 KB)

template<bool BIAS>
__global__ __launch_bounds__(256, 2) void gemm_pre(
    const __nv_bfloat16* __restrict__ Ah, const __nv_bfloat16* __restrict__ Al,
    const __nv_bfloat16* __restrict__ Bh, const __nv_bfloat16* __restrict__ Bl,
    const float* __restrict__ bias, float* __restrict__ C,
    int M, int N, int K)
{
    extern __shared__ __nv_bfloat16 smem[];

    const int tid  = threadIdx.x;
    const int lane = tid & 31;
    const int warp = tid >> 5;
    const int m_base = (warp & 3) * 32;
    const int n_base = (warp >> 2) * 64;
    const int blockM = blockIdx.y * 128;
    const int blockN = blockIdx.x * 128;

    const int aRow0 = tid >> 2, aC0 = (tid & 3) << 3;
    const int aRow1 = (tid + 256) >> 2, aC1 = ((tid + 256) & 3) << 3;
    const int bRow0 = tid >> 4, bC0 = (tid & 15) << 3;
    const int bRow1 = (tid + 256) >> 4, bC1 = ((tid + 256) & 15) << 3;

    float acc[2][8][4];
    #pragma unroll
    for (int i = 0; i < 2; i++)
        #pragma unroll
        for (int j = 0; j < 8; j++)
            #pragma unroll
            for (int q = 0; q < 4; q++) acc[i][j][q] = 0.f;

    auto load_tile = [&](int stage, int k0) {
        __nv_bfloat16* sAh = smem + stage * STAGE_ELS;
        __nv_bfloat16* sAl = sAh + A_ELS;
        __nv_bfloat16* sBh = sAl + A_ELS;
        __nv_bfloat16* sBl = sBh + B_ELS;
        cp16(sAh + aRow0 * APAD + aC0, Ah + (size_t)(blockM + aRow0) * K + k0 + aC0);
        cp16(sAh + aRow1 * APAD + aC1, Ah + (size_t)(blockM + aRow1) * K + k0 + aC1);
        cp16(sAl + aRow0 * APAD + aC0, Al + (size_t)(blockM + aRow0) * K + k0 + aC0);
        cp16(sAl + aRow1 * APAD + aC1, Al + (size_t)(blockM + aRow1) * K + k0 + aC1);
        cp16(sBh + bRow0 * BPAD + bC0, Bh + (size_t)(k0 + bRow0) * N + blockN + bC0);
        cp16(sBh + bRow1 * BPAD + bC1, Bh + (size_t)(k0 + bRow1) * N + blockN + bC1);
        cp16(sBl + bRow0 * BPAD + bC0, Bl + (size_t)(k0 + bRow0) * N + blockN + bC0);
        cp16(sBl + bRow1 * BPAD + bC1, Bl + (size_t)(k0 + bRow1) * N + blockN + bC1);
    };

    const int NT = K >> 5;   // K/32
    load_tile(0, 0);
    cp_commit();

    for (int kt = 0; kt < NT; kt++) {
        if (kt + 1 < NT) {
            load_tile((kt + 1) & 1, (kt + 1) << 5);
            cp_commit();
            cp_wait<1>();
        } else {
            cp_wait<0>();
        }
        __syncthreads();

        const __nv_bfloat16* sAh = smem + (kt & 1) * STAGE_ELS;
        const __nv_bfloat16* sAl = sAh + A_ELS;
        const __nv_bfloat16* sBh = sAl + A_ELS;
        const __nv_bfloat16* sBl = sBh + B_ELS;

        #pragma unroll
        for (int ks = 0; ks < 2; ks++) {
            const int kk = ks * 16;
            uint32_t ah[2][4], al[2][4];
            #pragma unroll
            for (int mf = 0; mf < 2; mf++) {
                const int row = m_base + mf * 16 + (lane & 15);
                const int col = kk + ((lane >> 4) << 3);
                ldsm_x4(ah[mf], sm_u32(sAh + row * APAD + col));
                ldsm_x4(al[mf], sm_u32(sAl + row * APAD + col));
            }
            #pragma unroll
            for (int ng = 0; ng < 4; ng++) {
                const int brow = kk + (lane & 15);
                const int bcol = n_base + ng * 16 + ((lane >> 4) << 3);
                uint32_t bh[4], bl[4];
                ldsm_x4_t(bh, sm_u32(sBh + brow * BPAD + bcol));
                ldsm_x4_t(bl, sm_u32(sBl + brow * BPAD + bcol));
                #pragma unroll
                for (int p = 0; p < 3; p++) {
                    const uint32_t* ap0 = (p == 2) ? al[0] : ah[0];
                    const uint32_t* ap1 = (p == 2) ? al[1] : ah[1];
                    const uint32_t* bp = (p == 1) ? bl : bh;
                    mma16816(acc[0][ng*2+0], ap0, bp + 0);
                    mma16816(acc[1][ng*2+0], ap1, bp + 0);
                    mma16816(acc[0][ng*2+1], ap0, bp + 2);
                    mma16816(acc[1][ng*2+1], ap1, bp + 2);
                }
            }
        }
        __syncthreads();
    }

    #pragma unroll
    for (int mf = 0; mf < 2; mf++) {
        const int r0 = blockM + m_base + mf * 16 + (lane >> 2);
        #pragma unroll
        for (int nf = 0; nf < 8; nf++) {
            const int cN = blockN + n_base + nf * 8 + (lane & 3) * 2;
            float2 v0 = make_float2(acc[mf][nf][0], acc[mf][nf][1]);
            float2 v1 = make_float2(acc[mf][nf][2], acc[mf][nf][3]);
            if (BIAS) {
                const float b0 = bias[cN], b1 = bias[cN + 1];
                v0.x += b0; v0.y += b1; v1.x += b0; v1.y += b1;
            }
            *(float2*)(C + (size_t)r0 * N + cN) = v0;
            *(float2*)(C + (size_t)(r0 + 8) * N + cN) = v1;
        }
    }
}

// ---------------------------------------------------------------------------
// Fused attention, SMALL-BLOCK layout: 1024 blocks x 128 threads.
// Per-thread math identical to R12 (1 query per thread, f32x2 FMA, no shuffle).
// 128 thr x ~160 regs = 20.5K regs -> 3 blocks/SM (regs), smem 32KB -> fits.
//   Blocks [0,512): spatial — (nt, h, half): 128 queries each; K/V staged in
//     KTILE=64 tiles (32KB smem).
//   Blocks [512,1024): temporal — one (n,s); K/V direct from gmem (as R12).
// Outputs bf16 hi/lo split.
// ---------------------------------------------------------------------------
#define KTILE 64
#define ATTN_SMEM (2 * KTILE * DH * 4)   // 32KB

__device__ __forceinline__ void store_hi_lo(
    __nv_bfloat16* oh, __nv_bfloat16* ol, size_t obase, const u64t* acc2,
    float inv)
{
    #pragma unroll
    for (int d8 = 0; d8 < 8; d8++) {
        uint4 uh, ul;
        uint16_t hh[8], lt[8];
        #pragma unroll
        for (int e2 = 0; e2 < 4; e2++) {
            float a0, a1;
            unpack2(acc2[d8 * 4 + e2], a0, a1);
            split2(a0 * inv, hh[e2*2+0], lt[e2*2+0]);
            split2(a1 * inv, hh[e2*2+1], lt[e2*2+1]);
        }
        uh.x = (uint32_t)hh[0] | ((uint32_t)hh[1] << 16);
        uh.y = (uint32_t)hh[2] | ((uint32_t)hh[3] << 16);
        uh.z = (uint32_t)hh[4] | ((uint32_t)hh[5] << 16);
        uh.w = (uint32_t)hh[6] | ((uint32_t)hh[7] << 16);
        ul.x = (uint32_t)lt[0] | ((uint32_t)lt[1] << 16);
        ul.y = (uint32_t)lt[2] | ((uint32_t)lt[3] << 16);
        ul.z = (uint32_t)lt[4] | ((uint32_t)lt[5] << 16);
        ul.w = (uint32_t)lt[6] | ((uint32_t)lt[7] << 16);
        *(uint4*)(oh + obase + d8 * 8) = uh;
        *(uint4*)(ol + obase + d8 * 8) = ul;
    }
}

__global__ __launch_bounds__(128) void fused_attn(
    const float* __restrict__ qkv,
    __nv_bfloat16* __restrict__ oh, __nv_bfloat16* __restrict__ ol)
{
    extern __shared__ float sm[];
    const int tid = threadIdx.x;
    const float scale = 0.125f;

    if (blockIdx.x < 512) {
        // -------- spatial: (nt, h, qhalf); 128 queries; KTILE staging ------
        float* Ks = sm;               // [KTILE][64]
        float* Vs = sm + KTILE * DH;  // [KTILE][64]
        const int inst2 = blockIdx.x;
        const int qhalf = inst2 & 1;
        const int inst = inst2 >> 1;
        const int h = inst & 7;
        const int nt = inst >> 3;
        const int q = qhalf * 128 + tid;

        const float* base = qkv + (size_t)nt * SB * THREE_D;

        u64t q2[32];
        {
            const u64t* qp2 = (const u64t*)(base + (size_t)q * THREE_D + h * DH);
            #pragma unroll
            for (int i = 0; i < 32; i++) q2[i] = qp2[i];
        }

        float m = -INFINITY, l = 0.f;
        u64t acc2[32];
        #pragma unroll
        for (int i = 0; i < 32; i++) acc2[i] = 0ull;

        for (int ktile = 0; ktile < SB; ktile += KTILE) {
            __syncthreads();   // previous tile fully consumed
            for (int i = tid; i < KTILE * 16; i += 128) {
                const int row = i >> 4;
                const int c4 = (i & 15) << 2;
                const float* rb = base + (size_t)(ktile + row) * THREE_D + h * DH;
                *(float4*)(Ks + row * DH + c4) = *(const float4*)(rb + 1024 + c4);
                *(float4*)(Vs + row * DH + c4) = *(const float4*)(rb + 2048 + c4);
            }
            __syncthreads();

            for (int jt = 0; jt < KTILE; jt += 8) {
                float s8[8];
                float tmax = -INFINITY;
                #pragma unroll
                for (int u = 0; u < 8; u++) {
                    const u64t* kj2 = (const u64t*)(Ks + (jt + u) * DH);
                    u64t d2a = 0ull, d2b = 0ull;
                    #pragma unroll
                    for (int i = 0; i < 32; i += 2) {
                        d2a = ffma2(q2[i],     kj2[i],     d2a);
                        d2b = ffma2(q2[i + 1], kj2[i + 1], d2b);
                    }
                    float a0, a1, b0, b1;
                    unpack2(d2a, a0, a1);
                    unpack2(d2b, b0, b1);
                    s8[u] = ((a0 + b0) + (a1 + b1)) * scale;
                    tmax = fmaxf(tmax, s8[u]);
                }
                const float mn = fmaxf(m, tmax);
                const float c = __expf(m - mn);
                l *= c;
                const u64t cc = pack2(c, c);
                #pragma unroll
                for (int i = 0; i < 32; i++) acc2[i] = ffma2(acc2[i], cc, 0ull);
                m = mn;
                #pragma unroll
                for (int u = 0; u < 8; u++) {
                    const float p = __expf(s8[u] - m);
                    l += p;
                    const u64t pp = pack2(p, p);
                    const u64t* vj2 = (const u64t*)(Vs + (jt + u) * DH);
                    #pragma unroll
                    for (int i = 0; i < 32; i++)
                        acc2[i] = ffma2(pp, vj2[i], acc2[i]);
                }
            }
        }

        const size_t obase = ((size_t)nt * SB + q) * DB + h * DH;  // cols [0,512)
        store_hi_lo(oh, ol, obase, acc2, 1.f / l);
    } else {
        // -------- temporal: one (n,s) per 128-thread block (R12 math) ------
        const int ns = blockIdx.x - 512;    // 0..511
        const int n = ns >> 8;
        const int s = ns & 255;
        const int h = tid & 7;
        const int t = tid >> 3;

        const size_t tstride = (size_t)SB * THREE_D;
        const float* rowbase = qkv + ((size_t)(n * TB) * SB + s) * THREE_D;

        u64t q2[32];
        {
            const u64t* qp2 = (const u64t*)(rowbase + t * tstride + 512 + h * DH);
            #pragma unroll
            for (int i = 0; i < 32; i++) q2[i] = qp2[i];
        }

        float sc[TB];
        float mmax = -INFINITY;
        #pragma unroll
        for (int j = 0; j < TB; j++) {
            const u64t* kj2 = (const u64t*)(rowbase + j * tstride + 1536 + h * DH);
            u64t d2a = 0ull, d2b = 0ull;
            #pragma unroll
            for (int i = 0; i < 32; i += 2) {
                d2a = ffma2(q2[i],     kj2[i],     d2a);
                d2b = ffma2(q2[i + 1], kj2[i + 1], d2b);
            }
            float a0, a1, b0, b1;
            unpack2(d2a, a0, a1);
            unpack2(d2b, b0, b1);
            sc[j] = ((a0 + b0) + (a1 + b1)) * scale;
            mmax = fmaxf(mmax, sc[j]);
        }
        float lsum = 0.f;
        #pragma unroll
        for (int j = 0; j < TB; j++) {
            sc[j] = __expf(sc[j] - mmax);
            lsum += sc[j];
        }

        u64t acc2[32];
        #pragma unroll
        for (int i = 0; i < 32; i++) acc2[i] = 0ull;
        #pragma unroll
        for (int j = 0; j < TB; j++) {
            const u64t pp = pack2(sc[j], sc[j]);
            const u64t* vj2 = (const u64t*)(rowbase + j * tstride + 2560 + h * DH);
            #pragma unroll
            for (int i = 0; i < 32; i++)
                acc2[i] = ffma2(pp, vj2[i], acc2[i]);
        }

        const size_t obase =
            ((size_t)(n * TB + t) * SB + s) * DB + 512 + h * DH;  // cols [512,1024)
        store_hi_lo(oh, ol, obase, acc2, 1.f / lsum);
    }
}

// ---------------------------------------------------------------------------
extern "C" void kernel_launch(void* const* d_in, const int* in_sizes, int n_in,
                              void* d_out, int out_size)
{
    const float* x     = (const float*)d_in[0];  // [2,16,256,1024]
    const float* Wqkv  = (const float*)d_in[1];  // [1024,3072]
    const float* Wproj = (const float*)d_in[2];  // [1024,1024]
    const float* bproj = (const float*)d_in[3];  // [1024]
    float* out = (float*)d_out;

    float *qkv_ptr;
    __nv_bfloat16 *xh, *xl, *wqh, *wql, *wph, *wpl, *ah, *al;
    cudaGetSymbolAddress((void**)&qkv_ptr, g_qkv);
    cudaGetSymbolAddress((void**)&xh, g_xh);
    cudaGetSymbolAddress((void**)&xl, g_xl);
    cudaGetSymbolAddress((void**)&wqh, g_wqh);
    cudaGetSymbolAddress((void**)&wql, g_wql);
    cudaGetSymbolAddress((void**)&wph, g_wph);
    cudaGetSymbolAddress((void**)&wpl, g_wpl);
    cudaGetSymbolAddress((void**)&ah, g_ah);
    cudaGetSymbolAddress((void**)&al, g_al);

    cudaFuncSetAttribute(gemm_pre<false>,
        cudaFuncAttributeMaxDynamicSharedMemorySize, GEMM_SMEM);
    cudaFuncSetAttribute(gemm_pre<true>,
        cudaFuncAttributeMaxDynamicSharedMemorySize, GEMM_SMEM);
    cudaFuncSetAttribute(fused_attn,
        cudaFuncAttributeMaxDynamicSharedMemorySize, ATTN_SMEM);

    // 0) pre-split inputs to bf16 hi/lo
    {
        int n4x = ROWS * DB / 4;
        split_kernel<<<n4x / 256, 256>>>(x, xh, xl, n4x);
        int n4q = DB * THREE_D / 4;
        split_kernel<<<n4q / 256, 256>>>(Wqkv, wqh, wql, n4q);
        int n4p = DB * DB / 4;
        split_kernel<<<n4p / 256, 256>>>(Wproj, wph, wpl, n4p);
    }

    // 1) qkv = x @ Wqkv : [8192,1024] x [1024,3072]
    {
        dim3 grid(THREE_D / 128, ROWS / 128);
        gemm_pre<false><<<grid, 256, GEMM_SMEM>>>(xh, xl, wqh, wql, nullptr,
                                                  qkv_ptr, ROWS, THREE_D, DB);
    }

    // 2) fused attention: spatial blocks [0,512), temporal [512,1024)
    fused_attn<<<1024, 128, ATTN_SMEM>>>(qkv_ptr, ah, al);

    // 3) out = attn @ Wproj + bproj : [8192,1024] x [1024,1024]
    {
        dim3 grid(DB / 128, ROWS / 128);
        gemm_pre<true><<<grid, 256, GEMM_SMEM>>>(ah, al, wph, wpl, bproj,
                                                 out, ROWS, DB, DB);
    }
}